// round 16
// baseline (speedup 1.0000x reference)
#include <cuda_runtime.h>
#include <cuda_fp16.h>
#include <mma.h>
#include <cstdint>

using namespace nvcuda;

#define NN 100000
#define NP 100032            // padded to multiple of 64
#define DD 128
#define EE 1600000
#define RR 4

#define SCAN_N   (RR * NN)
#define SCAN_BLK 512
#define SCAN_NBLK ((SCAN_N + SCAN_BLK - 1) / SCAN_BLK)

// ---------------- device scratch --------------------------------------------
__device__ __half  g_Yh[(size_t)NP * DD];      // transformed feats (fp16, 25.6MB)
__device__ __half  g_Ah[(size_t)NP * DD];      // input feats hi (fp16)
__device__ __half  g_Al[(size_t)NP * DD];      // input feats lo (fp16)
__device__ __half  g_Bh[2][(size_t)RR * DD * DD];  // W hi per layer
__device__ __half  g_Bl[2][(size_t)RR * DD * DD];  // W lo per layer
__device__ float   g_acc[(size_t)NN * DD];     // aggregation accumulator
__device__ int     g_deg[2 * SCAN_N];          // [0]=degout, [SCAN_N]=degin
__device__ int     g_off[SCAN_N];
__device__ int     g_cur[SCAN_N];
__device__ int     g_bsum[SCAN_NBLK];
__device__ float2  g_csr[(size_t)RR * EE];     // (src bits, weight)

// ---------------- operand pre-split ------------------------------------------
__global__ void presplit_kernel(const float* __restrict__ src,
                                __half* __restrict__ dh, __half* __restrict__ dl,
                                int nvalid4, int ntotal4) {
    int i = blockIdx.x * blockDim.x + threadIdx.x;
    if (i >= ntotal4) return;
    float4 v = (i < nvalid4) ? ((const float4*)src)[i]
                             : make_float4(0.f, 0.f, 0.f, 0.f);
    __half h0 = __float2half_rn(v.x), h1 = __float2half_rn(v.y);
    __half h2 = __float2half_rn(v.z), h3 = __float2half_rn(v.w);
    __half l0 = __float2half_rn(v.x - __half2float(h0));
    __half l1 = __float2half_rn(v.y - __half2float(h1));
    __half l2 = __float2half_rn(v.z - __half2float(h2));
    __half l3 = __float2half_rn(v.w - __half2float(h3));
    __half2 ph[2] = {__halves2half2(h0, h1), __halves2half2(h2, h3)};
    __half2 pl[2] = {__halves2half2(l0, l1), __halves2half2(l2, l3)};
    ((uint2*)dh)[i] = *(const uint2*)ph;
    ((uint2*)dl)[i] = *(const uint2*)pl;
}

// ---------------- setup kernels ---------------------------------------------

__global__ void deg_kernel(const int* __restrict__ src, const int* __restrict__ dst) {
    long long i = (long long)blockIdx.x * blockDim.x + threadIdx.x;
    if (i >= (long long)RR * EE) return;
    int r = (int)(i / EE);
    atomicAdd(&g_deg[r * NN + src[i]], 1);
    atomicAdd(&g_deg[SCAN_N + r * NN + dst[i]], 1);
}

__global__ void scan_a_kernel() {
    __shared__ int s[SCAN_BLK];
    int i = blockIdx.x * SCAN_BLK + threadIdx.x;
    s[threadIdx.x] = (i < SCAN_N) ? g_deg[SCAN_N + i] : 0;
    __syncthreads();
    for (int d = SCAN_BLK / 2; d > 0; d >>= 1) {
        if (threadIdx.x < d) s[threadIdx.x] += s[threadIdx.x + d];
        __syncthreads();
    }
    if (threadIdx.x == 0) g_bsum[blockIdx.x] = s[0];
}

__global__ void scan_b_kernel() {
    __shared__ int s[1024];
    int t = threadIdx.x;
    s[t] = (t < SCAN_NBLK) ? g_bsum[t] : 0;
    __syncthreads();
    for (int d = 1; d < 1024; d <<= 1) {
        int v = (t >= d) ? s[t - d] : 0;
        __syncthreads();
        s[t] += v;
        __syncthreads();
    }
    if (t < SCAN_NBLK) g_bsum[t] = (t == 0) ? 0 : s[t - 1];
}

__global__ void scan_c_kernel() {
    __shared__ int s[SCAN_BLK];
    int i = blockIdx.x * SCAN_BLK + threadIdx.x;
    int v = (i < SCAN_N) ? g_deg[SCAN_N + i] : 0;
    s[threadIdx.x] = v;
    __syncthreads();
    for (int d = 1; d < SCAN_BLK; d <<= 1) {
        int u = (threadIdx.x >= d) ? s[threadIdx.x - d] : 0;
        __syncthreads();
        s[threadIdx.x] += u;
        __syncthreads();
    }
    if (i < SCAN_N) {
        int ex = s[threadIdx.x] - v + g_bsum[blockIdx.x];
        g_off[i] = ex;
        g_cur[i] = ex;
    }
}

__global__ void fill_kernel(const int* __restrict__ src, const int* __restrict__ dst,
                            const float* __restrict__ ew) {
    long long i = (long long)blockIdx.x * blockDim.x + threadIdx.x;
    if (i >= (long long)RR * EE) return;
    int r = (int)(i / EE);
    int s = src[i], d = dst[i];
    float w = ew[i]
            * rsqrtf(fmaxf((float)g_deg[r * NN + s], 1.f))
            * rsqrtf(fmaxf((float)g_deg[SCAN_N + r * NN + d], 1.f));
    int p = atomicAdd(&g_cur[r * NN + d], 1);
    g_csr[p] = make_float2(__int_as_float(s), w);
}

// ---------------- sync-free fp16-split GEMM: Yh = half(A @ W) ----------------
__global__ __launch_bounds__(256) void gemm_fp16_kernel(
    const __half* __restrict__ Ah, const __half* __restrict__ Al,
    const __half* __restrict__ Bh, const __half* __restrict__ Bl)
{
    __shared__ float sStage[8][16][20];

    const int row0 = blockIdx.x * 64;
    const int tid = threadIdx.x;
    const int wid = tid >> 5;
    const int lane = tid & 31;
    const int wr = wid & 3;
    const int wc = wid >> 2;

    const __half* Ap = Ah + (size_t)(row0 + wr * 16) * DD;
    const __half* Alp = Al + (size_t)(row0 + wr * 16) * DD;

    wmma::fragment<wmma::accumulator, 16, 16, 16, float> acc[4];
#pragma unroll
    for (int i = 0; i < 4; i++) wmma::fill_fragment(acc[i], 0.f);

#pragma unroll
    for (int kc = 0; kc < DD; kc += 16) {
        wmma::fragment<wmma::matrix_a, 16, 16, 16, __half, wmma::row_major> ah, al;
        wmma::load_matrix_sync(ah, Ap + kc, DD);
        wmma::load_matrix_sync(al, Alp + kc, DD);
#pragma unroll
        for (int cg = 0; cg < 4; cg++) {
            int col = wc * 64 + cg * 16;
            wmma::fragment<wmma::matrix_b, 16, 16, 16, __half, wmma::row_major> bh, bl;
            wmma::load_matrix_sync(bh, Bh + (size_t)kc * DD + col, DD);
            wmma::load_matrix_sync(bl, Bl + (size_t)kc * DD + col, DD);
            wmma::mma_sync(acc[cg], ah, bh, acc[cg]);
            wmma::mma_sync(acc[cg], ah, bl, acc[cg]);
            wmma::mma_sync(acc[cg], al, bh, acc[cg]);
        }
    }

    const int rr = lane >> 1;
    const int cb = (lane & 1) * 8;
#pragma unroll
    for (int cg = 0; cg < 4; cg++) {
        wmma::store_matrix_sync(&sStage[wid][0][0], acc[cg], 20, wmma::mem_row_major);
        __syncwarp();
        const float* sp = &sStage[wid][rr][cb];
        __half2 h0 = __floats2half2_rn(sp[0], sp[1]);
        __half2 h1 = __floats2half2_rn(sp[2], sp[3]);
        __half2 h2 = __floats2half2_rn(sp[4], sp[5]);
        __half2 h3 = __floats2half2_rn(sp[6], sp[7]);
        int grow = row0 + wr * 16 + rr;
        int gcol = wc * 64 + cg * 16 + cb;
        __half2 pack[4] = {h0, h1, h2, h3};
        *(uint4*)(g_Yh + (size_t)grow * DD + gcol) = *(const uint4*)pack;
        __syncwarp();
    }
}

// ---------------- per-relation pull: 2 edges per instruction -----------------
// Warp per node. Half-warp h processes edge 2k+h; each lane covers 8 columns
// (uint4 of fp16). k-loop = 16 iters per 32-edge batch. shfl_xor(16) combine.
__global__ __launch_bounds__(256) void pull_r_kernel(int r, int first)
{
    int warp = (blockIdx.x * blockDim.x + threadIdx.x) >> 5;
    int lane = threadIdx.x & 31;
    if (warp >= NN) return;
    int idx = r * NN + warp;
    const float2* eb = g_csr + g_off[idx];
    int cnt = g_deg[SCAN_N + idx];
    const int h = lane >> 4;
    const int co = (lane & 15) * 8;

    float a[8] = {0.f, 0.f, 0.f, 0.f, 0.f, 0.f, 0.f, 0.f};

    for (int j = 0; j < cnt; j += 32) {
        int m = cnt - j; if (m > 32) m = 32;
        float2 er = (lane < m) ? eb[j + lane] : make_float2(0.f, 0.f);
        int si = __float_as_int(er.x);
        int kmax = (m + 1) >> 1;
#pragma unroll 4
        for (int k = 0; k < kmax; k++) {
            int esel = 2 * k + h;                       // may be == m (w=0, safe)
            int s   = __shfl_sync(0xffffffffu, si, esel);
            float w = __shfl_sync(0xffffffffu, er.y, esel);
            uint4 rv = *(const uint4*)(g_Yh + (size_t)s * DD + co);
            float2 f0 = __half22float2(*(__half2*)&rv.x);
            float2 f1 = __half22float2(*(__half2*)&rv.y);
            float2 f2 = __half22float2(*(__half2*)&rv.z);
            float2 f3 = __half22float2(*(__half2*)&rv.w);
            a[0] += f0.x * w; a[1] += f0.y * w; a[2] += f1.x * w; a[3] += f1.y * w;
            a[4] += f2.x * w; a[5] += f2.y * w; a[6] += f3.x * w; a[7] += f3.y * w;
        }
    }

    // combine the two half-warp partial sums
#pragma unroll
    for (int t = 0; t < 8; t++)
        a[t] += __shfl_xor_sync(0xffffffffu, a[t], 16);

    if (lane < 16) {
        float* accp = g_acc + (size_t)warp * DD + co;
        if (!first) {
            float4 o0 = *(const float4*)accp;
            float4 o1 = *(const float4*)(accp + 4);
            a[0] += o0.x; a[1] += o0.y; a[2] += o0.z; a[3] += o0.w;
            a[4] += o1.x; a[5] += o1.y; a[6] += o1.z; a[7] += o1.w;
        }
        *(float4*)accp       = make_float4(a[0], a[1], a[2], a[3]);
        *(float4*)(accp + 4) = make_float4(a[4], a[5], a[6], a[7]);
    }
}

// layer-1 epilogue: h1 = relu(acc + bsum), written directly as fp16 hi/lo split
__global__ void bias_relu_split_kernel(const float* __restrict__ b) {
    int i = blockIdx.x * blockDim.x + threadIdx.x;
    if (i >= NN * DD / 4) return;
    int c = (i * 4) & (DD - 1);
    float4 v = ((const float4*)g_acc)[i];
    float o0 = fmaxf(v.x + b[c]   + b[DD + c]   + b[2*DD + c]   + b[3*DD + c],   0.f);
    float o1 = fmaxf(v.y + b[c+1] + b[DD + c+1] + b[2*DD + c+1] + b[3*DD + c+1], 0.f);
    float o2 = fmaxf(v.z + b[c+2] + b[DD + c+2] + b[2*DD + c+2] + b[3*DD + c+2], 0.f);
    float o3 = fmaxf(v.w + b[c+3] + b[DD + c+3] + b[2*DD + c+3] + b[3*DD + c+3], 0.f);
    __half h0 = __float2half_rn(o0), h1 = __float2half_rn(o1);
    __half h2 = __float2half_rn(o2), h3 = __float2half_rn(o3);
    __half l0 = __float2half_rn(o0 - __half2float(h0));
    __half l1 = __float2half_rn(o1 - __half2float(h1));
    __half l2 = __float2half_rn(o2 - __half2float(h2));
    __half l3 = __float2half_rn(o3 - __half2float(h3));
    __half2 ph[2] = {__halves2half2(h0, h1), __halves2half2(h2, h3)};
    __half2 pl[2] = {__halves2half2(l0, l1), __halves2half2(l2, l3)};
    ((uint2*)g_Ah)[i] = *(const uint2*)ph;
    ((uint2*)g_Al)[i] = *(const uint2*)pl;
}

// layer-2 epilogue: out = relu(acc + bsum) fp32
__global__ void bias_relu_kernel(const float* __restrict__ b, float* __restrict__ out) {
    int i = blockIdx.x * blockDim.x + threadIdx.x;
    if (i >= NN * DD) return;
    int j = i & (DD - 1);
    float bs = b[j] + b[DD + j] + b[2 * DD + j] + b[3 * DD + j];
    out[i] = fmaxf(g_acc[i] + bs, 0.f);
}

// ---------------- launch ----------------------------------------------------

static void* s_deg_ptr = nullptr;

extern "C" void kernel_launch(void* const* d_in, const int* in_sizes, int n_in,
                              void* d_out, int out_size)
{
    if (!s_deg_ptr) cudaGetSymbolAddress(&s_deg_ptr, g_deg);

    const float* x   = (const float*)d_in[0];
    const int*   src = (const int*)d_in[1];
    const int*   dst = (const int*)d_in[2];
    const float* ew  = (const float*)d_in[3];
    const float* W1  = (const float*)d_in[4];
    const float* b1  = (const float*)d_in[5];
    const float* W2  = (const float*)d_in[6];
    const float* b2  = (const float*)d_in[7];
    float* out = (float*)d_out;

    const int T = 256;
    const long long RE = (long long)RR * EE;
    const int edge_blocks = (int)((RE + T - 1) / T);
    const int ggrid = NP / 64;
    const int pull_blocks = (NN * 32 + T - 1) / T;
    const int elem_blocks = (NN * DD + T - 1) / T;
    const int hsplit_blocks = (NP * DD / 4 + T - 1) / T;
    const int wsplit_blocks = (RR * DD * DD / 4 + T - 1) / T;

    __half *Ah, *Al, *Bh0, *Bl0, *Bh1, *Bl1;
    cudaGetSymbolAddress((void**)&Ah, g_Ah);
    cudaGetSymbolAddress((void**)&Al, g_Al);
    cudaGetSymbolAddress((void**)&Bh0, g_Bh);  Bh1 = Bh0 + (size_t)RR * DD * DD;
    cudaGetSymbolAddress((void**)&Bl0, g_Bl);  Bl1 = Bl0 + (size_t)RR * DD * DD;

    cudaMemsetAsync(s_deg_ptr, 0, 2 * SCAN_N * sizeof(int));
    presplit_kernel<<<hsplit_blocks, T>>>(x, Ah, Al, NN*DD/4, NP*DD/4);
    presplit_kernel<<<wsplit_blocks, T>>>(W1, Bh0, Bl0, RR*DD*DD/4, RR*DD*DD/4);
    presplit_kernel<<<wsplit_blocks, T>>>(W2, Bh1, Bl1, RR*DD*DD/4, RR*DD*DD/4);
    deg_kernel<<<edge_blocks, T>>>(src, dst);
    gemm_fp16_kernel<<<ggrid, T>>>(Ah, Al, Bh0, Bl0);      // r=0
    scan_a_kernel<<<SCAN_NBLK, SCAN_BLK>>>();
    scan_b_kernel<<<1, 1024>>>();
    scan_c_kernel<<<SCAN_NBLK, SCAN_BLK>>>();
    fill_kernel<<<edge_blocks, T>>>(src, dst, ew);

    // ---- layer 1 (gemm r=0 already issued) ----
    pull_r_kernel<<<pull_blocks, T>>>(0, 1);
    for (int r = 1; r < RR; r++) {
        gemm_fp16_kernel<<<ggrid, T>>>(Ah, Al,
                                       Bh0 + (size_t)r * DD * DD,
                                       Bl0 + (size_t)r * DD * DD);
        pull_r_kernel<<<pull_blocks, T>>>(r, 0);
    }
    bias_relu_split_kernel<<<(NN * DD / 4 + T - 1) / T, T>>>(b1);

    // ---- layer 2 ----
    for (int r = 0; r < RR; r++) {
        gemm_fp16_kernel<<<ggrid, T>>>(Ah, Al,
                                       Bh1 + (size_t)r * DD * DD,
                                       Bl1 + (size_t)r * DD * DD);
        pull_r_kernel<<<pull_blocks, T>>>(r, r == 0);
    }
    bias_relu_kernel<<<elem_blocks, T>>>(b2, out);
}

// round 17
// speedup vs baseline: 1.0322x; 1.0322x over previous
#include <cuda_runtime.h>
#include <cuda_fp16.h>
#include <mma.h>
#include <cstdint>

using namespace nvcuda;

#define NN 100000
#define NP 100032            // padded to multiple of 64
#define DD 128
#define EE 1600000
#define RR 4

#define SCAN_N   (RR * NN)
#define SCAN_BLK 512
#define SCAN_NBLK ((SCAN_N + SCAN_BLK - 1) / SCAN_BLK)

// ---------------- device scratch --------------------------------------------
__device__ __half  g_Yh[(size_t)NP * DD];      // transformed feats (fp16, 25.6MB)
__device__ __half  g_Ah[(size_t)NP * DD];      // input feats hi (fp16)
__device__ __half  g_Al[(size_t)NP * DD];      // input feats lo (fp16)
__device__ __half  g_Bh[2][(size_t)RR * DD * DD];  // W hi per layer
__device__ __half  g_Bl[2][(size_t)RR * DD * DD];  // W lo per layer
__device__ float   g_acc[(size_t)NN * DD];     // aggregation accumulator
__device__ int     g_deg[2 * SCAN_N];          // [0]=degout, [SCAN_N]=degin
__device__ int     g_off[SCAN_N];
__device__ int     g_cur[SCAN_N];
__device__ int     g_bsum[SCAN_NBLK];
__device__ float2  g_csr[(size_t)RR * EE];     // (src bits, weight)

// ---------------- operand pre-split ------------------------------------------
__global__ void presplit_kernel(const float* __restrict__ src,
                                __half* __restrict__ dh, __half* __restrict__ dl,
                                int nvalid4, int ntotal4) {
    int i = blockIdx.x * blockDim.x + threadIdx.x;
    if (i >= ntotal4) return;
    float4 v = (i < nvalid4) ? ((const float4*)src)[i]
                             : make_float4(0.f, 0.f, 0.f, 0.f);
    __half h0 = __float2half_rn(v.x), h1 = __float2half_rn(v.y);
    __half h2 = __float2half_rn(v.z), h3 = __float2half_rn(v.w);
    __half l0 = __float2half_rn(v.x - __half2float(h0));
    __half l1 = __float2half_rn(v.y - __half2float(h1));
    __half l2 = __float2half_rn(v.z - __half2float(h2));
    __half l3 = __float2half_rn(v.w - __half2float(h3));
    __half2 ph[2] = {__halves2half2(h0, h1), __halves2half2(h2, h3)};
    __half2 pl[2] = {__halves2half2(l0, l1), __halves2half2(l2, l3)};
    ((uint2*)dh)[i] = *(const uint2*)ph;
    ((uint2*)dl)[i] = *(const uint2*)pl;
}

// ---------------- setup kernels ---------------------------------------------

__global__ void deg_kernel(const int* __restrict__ src, const int* __restrict__ dst) {
    long long i = (long long)blockIdx.x * blockDim.x + threadIdx.x;
    if (i >= (long long)RR * EE) return;
    int r = (int)(i / EE);
    atomicAdd(&g_deg[r * NN + src[i]], 1);
    atomicAdd(&g_deg[SCAN_N + r * NN + dst[i]], 1);
}

__global__ void scan_a_kernel() {
    __shared__ int s[SCAN_BLK];
    int i = blockIdx.x * SCAN_BLK + threadIdx.x;
    s[threadIdx.x] = (i < SCAN_N) ? g_deg[SCAN_N + i] : 0;
    __syncthreads();
    for (int d = SCAN_BLK / 2; d > 0; d >>= 1) {
        if (threadIdx.x < d) s[threadIdx.x] += s[threadIdx.x + d];
        __syncthreads();
    }
    if (threadIdx.x == 0) g_bsum[blockIdx.x] = s[0];
}

__global__ void scan_b_kernel() {
    __shared__ int s[1024];
    int t = threadIdx.x;
    s[t] = (t < SCAN_NBLK) ? g_bsum[t] : 0;
    __syncthreads();
    for (int d = 1; d < 1024; d <<= 1) {
        int v = (t >= d) ? s[t - d] : 0;
        __syncthreads();
        s[t] += v;
        __syncthreads();
    }
    if (t < SCAN_NBLK) g_bsum[t] = (t == 0) ? 0 : s[t - 1];
}

__global__ void scan_c_kernel() {
    __shared__ int s[SCAN_BLK];
    int i = blockIdx.x * SCAN_BLK + threadIdx.x;
    int v = (i < SCAN_N) ? g_deg[SCAN_N + i] : 0;
    s[threadIdx.x] = v;
    __syncthreads();
    for (int d = 1; d < SCAN_BLK; d <<= 1) {
        int u = (threadIdx.x >= d) ? s[threadIdx.x - d] : 0;
        __syncthreads();
        s[threadIdx.x] += u;
        __syncthreads();
    }
    if (i < SCAN_N) {
        int ex = s[threadIdx.x] - v + g_bsum[blockIdx.x];
        g_off[i] = ex;
        g_cur[i] = ex;
    }
}

__global__ void fill_kernel(const int* __restrict__ src, const int* __restrict__ dst,
                            const float* __restrict__ ew) {
    long long i = (long long)blockIdx.x * blockDim.x + threadIdx.x;
    if (i >= (long long)RR * EE) return;
    int r = (int)(i / EE);
    int s = src[i], d = dst[i];
    float w = ew[i]
            * rsqrtf(fmaxf((float)g_deg[r * NN + s], 1.f))
            * rsqrtf(fmaxf((float)g_deg[SCAN_N + r * NN + d], 1.f));
    int p = atomicAdd(&g_cur[r * NN + d], 1);
    g_csr[p] = make_float2(__int_as_float(s), w);
}

// ---------------- sync-free fp16-split GEMM: Yh = half(A @ W) ----------------
__global__ __launch_bounds__(256) void gemm_fp16_kernel(
    const __half* __restrict__ Ah, const __half* __restrict__ Al,
    const __half* __restrict__ Bh, const __half* __restrict__ Bl)
{
    __shared__ float sStage[8][16][20];

    const int row0 = blockIdx.x * 64;
    const int tid = threadIdx.x;
    const int wid = tid >> 5;
    const int lane = tid & 31;
    const int wr = wid & 3;
    const int wc = wid >> 2;

    const __half* Ap = Ah + (size_t)(row0 + wr * 16) * DD;
    const __half* Alp = Al + (size_t)(row0 + wr * 16) * DD;

    wmma::fragment<wmma::accumulator, 16, 16, 16, float> acc[4];
#pragma unroll
    for (int i = 0; i < 4; i++) wmma::fill_fragment(acc[i], 0.f);

#pragma unroll
    for (int kc = 0; kc < DD; kc += 16) {
        wmma::fragment<wmma::matrix_a, 16, 16, 16, __half, wmma::row_major> ah, al;
        wmma::load_matrix_sync(ah, Ap + kc, DD);
        wmma::load_matrix_sync(al, Alp + kc, DD);
#pragma unroll
        for (int cg = 0; cg < 4; cg++) {
            int col = wc * 64 + cg * 16;
            wmma::fragment<wmma::matrix_b, 16, 16, 16, __half, wmma::row_major> bh, bl;
            wmma::load_matrix_sync(bh, Bh + (size_t)kc * DD + col, DD);
            wmma::load_matrix_sync(bl, Bl + (size_t)kc * DD + col, DD);
            wmma::mma_sync(acc[cg], ah, bh, acc[cg]);
            wmma::mma_sync(acc[cg], ah, bl, acc[cg]);
            wmma::mma_sync(acc[cg], al, bh, acc[cg]);
        }
    }

    const int rr = lane >> 1;
    const int cb = (lane & 1) * 8;
#pragma unroll
    for (int cg = 0; cg < 4; cg++) {
        wmma::store_matrix_sync(&sStage[wid][0][0], acc[cg], 20, wmma::mem_row_major);
        __syncwarp();
        const float* sp = &sStage[wid][rr][cb];
        __half2 h0 = __floats2half2_rn(sp[0], sp[1]);
        __half2 h1 = __floats2half2_rn(sp[2], sp[3]);
        __half2 h2 = __floats2half2_rn(sp[4], sp[5]);
        __half2 h3 = __floats2half2_rn(sp[6], sp[7]);
        int grow = row0 + wr * 16 + rr;
        int gcol = wc * 64 + cg * 16 + cb;
        __half2 pack[4] = {h0, h1, h2, h3};
        *(uint4*)(g_Yh + (size_t)grow * DD + gcol) = *(const uint4*)pack;
        __syncwarp();
    }
}

// ---------------- per-relation pull: broadcast record loads, no shfl ---------
// Warp per node; all lanes load the SAME edge record (broadcast, L1-resident
// line covers 16 records), so each gather depends only on its own record load.
__global__ __launch_bounds__(256) void pull_r_kernel(int r, int first)
{
    int warp = (blockIdx.x * blockDim.x + threadIdx.x) >> 5;
    int lane = threadIdx.x & 31;
    if (warp >= NN) return;
    int idx = r * NN + warp;
    const float2* __restrict__ eb = g_csr + g_off[idx];
    int cnt = g_deg[SCAN_N + idx];
    const int co = lane * 4;

    float4 a0 = make_float4(0.f, 0.f, 0.f, 0.f);

#pragma unroll 8
    for (int k = 0; k < cnt; k++) {
        float2 e = eb[k];                         // broadcast load
        int s = __float_as_int(e.x);
        float w = e.y;
        uint2 rv = *(const uint2*)(g_Yh + (size_t)s * DD + co);
        float2 f0 = __half22float2(*(__half2*)&rv.x);
        float2 f1 = __half22float2(*(__half2*)&rv.y);
        a0.x += f0.x * w; a0.y += f0.y * w; a0.z += f1.x * w; a0.w += f1.y * w;
    }

    float* accp = g_acc + (size_t)warp * DD + co;
    if (!first) {
        float4 old = *(const float4*)accp;
        a0.x += old.x; a0.y += old.y; a0.z += old.z; a0.w += old.w;
    }
    *(float4*)accp = a0;
}

// layer-1 epilogue: h1 = relu(acc + bsum), written directly as fp16 hi/lo split
__global__ void bias_relu_split_kernel(const float* __restrict__ b) {
    int i = blockIdx.x * blockDim.x + threadIdx.x;
    if (i >= NN * DD / 4) return;
    int c = (i * 4) & (DD - 1);
    float4 v = ((const float4*)g_acc)[i];
    float o0 = fmaxf(v.x + b[c]   + b[DD + c]   + b[2*DD + c]   + b[3*DD + c],   0.f);
    float o1 = fmaxf(v.y + b[c+1] + b[DD + c+1] + b[2*DD + c+1] + b[3*DD + c+1], 0.f);
    float o2 = fmaxf(v.z + b[c+2] + b[DD + c+2] + b[2*DD + c+2] + b[3*DD + c+2], 0.f);
    float o3 = fmaxf(v.w + b[c+3] + b[DD + c+3] + b[2*DD + c+3] + b[3*DD + c+3], 0.f);
    __half h0 = __float2half_rn(o0), h1 = __float2half_rn(o1);
    __half h2 = __float2half_rn(o2), h3 = __float2half_rn(o3);
    __half l0 = __float2half_rn(o0 - __half2float(h0));
    __half l1 = __float2half_rn(o1 - __half2float(h1));
    __half l2 = __float2half_rn(o2 - __half2float(h2));
    __half l3 = __float2half_rn(o3 - __half2float(h3));
    __half2 ph[2] = {__halves2half2(h0, h1), __halves2half2(h2, h3)};
    __half2 pl[2] = {__halves2half2(l0, l1), __halves2half2(l2, l3)};
    ((uint2*)g_Ah)[i] = *(const uint2*)ph;
    ((uint2*)g_Al)[i] = *(const uint2*)pl;
}

// layer-2 epilogue: out = relu(acc + bsum) fp32
__global__ void bias_relu_kernel(const float* __restrict__ b, float* __restrict__ out) {
    int i = blockIdx.x * blockDim.x + threadIdx.x;
    if (i >= NN * DD) return;
    int j = i & (DD - 1);
    float bs = b[j] + b[DD + j] + b[2 * DD + j] + b[3 * DD + j];
    out[i] = fmaxf(g_acc[i] + bs, 0.f);
}

// ---------------- launch ----------------------------------------------------

static void* s_deg_ptr = nullptr;

extern "C" void kernel_launch(void* const* d_in, const int* in_sizes, int n_in,
                              void* d_out, int out_size)
{
    if (!s_deg_ptr) cudaGetSymbolAddress(&s_deg_ptr, g_deg);

    const float* x   = (const float*)d_in[0];
    const int*   src = (const int*)d_in[1];
    const int*   dst = (const int*)d_in[2];
    const float* ew  = (const float*)d_in[3];
    const float* W1  = (const float*)d_in[4];
    const float* b1  = (const float*)d_in[5];
    const float* W2  = (const float*)d_in[6];
    const float* b2  = (const float*)d_in[7];
    float* out = (float*)d_out;

    const int T = 256;
    const long long RE = (long long)RR * EE;
    const int edge_blocks = (int)((RE + T - 1) / T);
    const int ggrid = NP / 64;
    const int pull_blocks = (NN * 32 + T - 1) / T;
    const int elem_blocks = (NN * DD + T - 1) / T;
    const int hsplit_blocks = (NP * DD / 4 + T - 1) / T;
    const int wsplit_blocks = (RR * DD * DD / 4 + T - 1) / T;

    __half *Ah, *Al, *Bh0, *Bl0, *Bh1, *Bl1;
    cudaGetSymbolAddress((void**)&Ah, g_Ah);
    cudaGetSymbolAddress((void**)&Al, g_Al);
    cudaGetSymbolAddress((void**)&Bh0, g_Bh);  Bh1 = Bh0 + (size_t)RR * DD * DD;
    cudaGetSymbolAddress((void**)&Bl0, g_Bl);  Bl1 = Bl0 + (size_t)RR * DD * DD;

    cudaMemsetAsync(s_deg_ptr, 0, 2 * SCAN_N * sizeof(int));
    presplit_kernel<<<hsplit_blocks, T>>>(x, Ah, Al, NN*DD/4, NP*DD/4);
    presplit_kernel<<<wsplit_blocks, T>>>(W1, Bh0, Bl0, RR*DD*DD/4, RR*DD*DD/4);
    presplit_kernel<<<wsplit_blocks, T>>>(W2, Bh1, Bl1, RR*DD*DD/4, RR*DD*DD/4);
    deg_kernel<<<edge_blocks, T>>>(src, dst);
    gemm_fp16_kernel<<<ggrid, T>>>(Ah, Al, Bh0, Bl0);      // r=0
    scan_a_kernel<<<SCAN_NBLK, SCAN_BLK>>>();
    scan_b_kernel<<<1, 1024>>>();
    scan_c_kernel<<<SCAN_NBLK, SCAN_BLK>>>();
    fill_kernel<<<edge_blocks, T>>>(src, dst, ew);

    // ---- layer 1 (gemm r=0 already issued) ----
    pull_r_kernel<<<pull_blocks, T>>>(0, 1);
    for (int r = 1; r < RR; r++) {
        gemm_fp16_kernel<<<ggrid, T>>>(Ah, Al,
                                       Bh0 + (size_t)r * DD * DD,
                                       Bl0 + (size_t)r * DD * DD);
        pull_r_kernel<<<pull_blocks, T>>>(r, 0);
    }
    bias_relu_split_kernel<<<(NN * DD / 4 + T - 1) / T, T>>>(b1);

    // ---- layer 2 ----
    for (int r = 0; r < RR; r++) {
        gemm_fp16_kernel<<<ggrid, T>>>(Ah, Al,
                                       Bh1 + (size_t)r * DD * DD,
                                       Bl1 + (size_t)r * DD * DD);
        pull_r_kernel<<<pull_blocks, T>>>(r, r == 0);
    }
    bias_relu_kernel<<<elem_blocks, T>>>(b2, out);
}